// round 9
// baseline (speedup 1.0000x reference)
#include <cuda_runtime.h>
#include <cstddef>

// 2-layer tanh RNN (B=2048,T=512,I=8,H=64)+FC.
// R8: layer-fused pipeline. Phase t computes h0(t) AND h1(t-1) (both consume
// h0(t-1): shared LDS reads), one barrier/phase. Weights in registers,
// k-split-8, conflict-free rotated h layout (R7). x@Wih0+b0 precomputed.

#define TT 512
typedef unsigned long long u64;

__device__ float g_pre0[(size_t)2048 * TT * 64];   // [B][t][j] = b0 + Wih0@x

static __device__ __forceinline__ void fma2(u64& a, u64 u, u64 v) {
    asm("fma.rn.f32x2 %0, %1, %2, %0;" : "+l"(a) : "l"(u), "l"(v));
}
static __device__ __forceinline__ u64 mul2(u64 u, u64 v) {
    u64 r; asm("mul.rn.f32x2 %0, %1, %2;" : "=l"(r) : "l"(u), "l"(v)); return r;
}
static __device__ __forceinline__ u64 add2(u64 a, u64 b) {
    u64 r; asm("add.rn.f32x2 %0, %1, %2;" : "=l"(r) : "l"(a), "l"(b)); return r;
}
static __device__ __forceinline__ u64 pack2(float a, float b) {
    u64 r; asm("mov.b64 %0, {%1, %2};" : "=l"(r) : "f"(a), "f"(b)); return r;
}
static __device__ __forceinline__ void unpack2(u64 v, float& a, float& b) {
    asm("mov.b64 {%0, %1}, %2;" : "=f"(a), "=f"(b) : "l"(v));
}
static __device__ __forceinline__ float ftanh(float s) {
    const float e = __expf(2.0f * s);
    return 1.0f - __fdividef(2.0f, e + 1.0f);
}
static __device__ __forceinline__ u64 shx(u64 v, int m) {
    return __shfl_xor_sync(0xffffffffu, v, m, 32);
}

// pre0[b][t][j] = bi0[j]+bh0[j] + sum_i x[b][t][i]*Wih0[j][i]; coalesced.
__global__ void __launch_bounds__(256)
pre0_kernel(const float* __restrict__ x, const float* __restrict__ Wih0,
            const float* __restrict__ bi0, const float* __restrict__ bh0)
{
    const size_t g   = (size_t)blockIdx.x * 256 + threadIdx.x;
    const size_t pos = g >> 4;              // B*TT + t
    const int    jq  = ((int)g & 15) * 4;
    const float4 x0 = reinterpret_cast<const float4*>(x)[pos * 2];
    const float4 x1 = reinterpret_cast<const float4*>(x)[pos * 2 + 1];
    float4 o; float* op = &o.x;
#pragma unroll
    for (int jj = 0; jj < 4; jj++) {
        const int j = jq + jj;
        const float4 w0 = reinterpret_cast<const float4*>(Wih0)[j * 2];
        const float4 w1 = reinterpret_cast<const float4*>(Wih0)[j * 2 + 1];
        op[jj] = bi0[j] + bh0[j]
               + w0.x*x0.x + w0.y*x0.y + w0.z*x0.z + w0.w*x0.w
               + w1.x*x1.x + w1.y*x1.y + w1.z*x1.z + w1.w*x1.w;
    }
    reinterpret_cast<float4*>(g_pre0)[pos * 16 + (jq >> 2)] = o;
}

__global__ void __launch_bounds__(512, 1)
rnn_main(const float* __restrict__ Whh0, const float* __restrict__ Wih1,
         const float* __restrict__ Whh1,
         const float* __restrict__ bi1,  const float* __restrict__ bh1,
         const float* __restrict__ fcw,  const float* __restrict__ fcb,
         float* __restrict__ out)
{
    __shared__ __align__(16) float h0s[2][16 * 64];
    __shared__ __align__(16) float h1s[2][16 * 64];

    const int tid  = threadIdx.x;
    const int lane = tid & 31;
    const int w    = tid >> 5;       // rows j0..j0+3
    const int b    = lane & 3;
    const int kg   = lane >> 2;      // k in [8kg, 8kg+8)
    const int s    = kg & 1;         // owned row-pair
    const int j0   = w * 4;
    const int g    = (b & 1) | ((b & 2) << 1);
    const int mychunk = kg >> 1;

    for (int i = tid; i < 16 * 64; i += 512) {
        h0s[1][i] = 0.f; h1s[0][i] = 0.f; h1s[1][i] = 0.f;
    }

    const int ofA0 = b * 64 + (((2 * kg     + g) & 15) << 2);
    const int ofB0 = b * 64 + (((2 * kg + 1 + g) & 15) << 2);
    const int sto  = (mychunk * 4 + b) * 64 + (((w + g) & 15) << 2) + 2 * s;

    // Weights in registers; acc slot q covers row-pair (q^s).
    u64 wa[2][2][4], wb[2][2][4], wc[2][2][4];
#pragma unroll
    for (int q = 0; q < 2; q++) {
        const int jA = j0 + 2 * (q ^ s);
#pragma unroll
        for (int h = 0; h < 2; h++) {
            const int base = ((jA + h) * 64 + kg * 8) >> 1;
#pragma unroll
            for (int kk = 0; kk < 4; kk++) {
                wa[q][h][kk] = reinterpret_cast<const u64*>(Whh0)[base + kk];
                wb[q][h][kk] = reinterpret_cast<const u64*>(Wih1)[base + kk];
                wc[q][h][kk] = reinterpret_cast<const u64*>(Whh1)[base + kk];
            }
        }
    }
    const u64 bz1 = pack2(bi1[j0+2*s] + bh1[j0+2*s], bi1[j0+2*s+1] + bh1[j0+2*s+1]);

    // pre0 pointer for owned (batch, row-pair); prefetch t=0.
    const float* pp = g_pre0 +
        ((size_t)(blockIdx.x * 16 + mychunk * 4 + b) * TT) * 64 + (j0 + 2 * s);
    u64 preC = *reinterpret_cast<const u64*>(pp);

    __syncthreads();

#pragma unroll 1
    for (int t = 0; t < TT; t++) {
        const int p = t & 1, pq = p ^ 1;

        // prefetch next phase's pre0 (clamped at the end; value unused then)
        const float* ppn = pp + ((t + 1 < TT) ? 64 : 0);
        const u64 preN = *reinterpret_cast<const u64*>(ppn);
        pp = ppn;

        u64 keep0, keep1;
#pragma unroll
        for (int bi = 0; bi < 4; bi++) {
            const u64* qa0 = reinterpret_cast<const u64*>(&h0s[pq][ofA0 + bi*256]);
            const u64* qb0 = reinterpret_cast<const u64*>(&h0s[pq][ofB0 + bi*256]);
            const u64 u0 = qa0[0], u1 = qa0[1], u2 = qb0[0], u3 = qb0[1];
            u64 a0[2][2], a1[2][2];
#pragma unroll
            for (int q = 0; q < 2; q++)
#pragma unroll
                for (int h = 0; h < 2; h++) {
                    a0[q][h] = mul2(wa[q][h][0], u0);
                    fma2(a0[q][h], wa[q][h][1], u1);
                    fma2(a0[q][h], wa[q][h][2], u2);
                    fma2(a0[q][h], wa[q][h][3], u3);
                    a1[q][h] = mul2(wb[q][h][0], u0);
                    fma2(a1[q][h], wb[q][h][1], u1);
                    fma2(a1[q][h], wb[q][h][2], u2);
                    fma2(a1[q][h], wb[q][h][3], u3);
                }
            const u64* qa1 = reinterpret_cast<const u64*>(&h1s[pq][ofA0 + bi*256]);
            const u64* qb1 = reinterpret_cast<const u64*>(&h1s[pq][ofB0 + bi*256]);
            const u64 z0 = qa1[0], z1 = qa1[1], z2 = qb1[0], z3 = qb1[1];
#pragma unroll
            for (int q = 0; q < 2; q++)
#pragma unroll
                for (int h = 0; h < 2; h++) {
                    fma2(a1[q][h], wc[q][h][0], z0);
                    fma2(a1[q][h], wc[q][h][1], z1);
                    fma2(a1[q][h], wc[q][h][2], z2);
                    fma2(a1[q][h], wc[q][h][3], z3);
                }
            // horizontal fold
            u64 v00, v01, v10, v11;
            {
                float l0,m0,l1,m1;
                unpack2(a0[0][0],l0,m0); unpack2(a0[0][1],l1,m1);
                v00 = pack2(l0+m0, l1+m1);
                unpack2(a0[1][0],l0,m0); unpack2(a0[1][1],l1,m1);
                v01 = pack2(l0+m0, l1+m1);
                unpack2(a1[0][0],l0,m0); unpack2(a1[0][1],l1,m1);
                v10 = pack2(l0+m0, l1+m1);
                unpack2(a1[1][0],l0,m0); unpack2(a1[1][1],l1,m1);
                v11 = pack2(l0+m0, l1+m1);
            }
            // two independent 3-round reductions (overlapping latency)
            u64 r0 = add2(v00, shx(v01, 4));
            u64 r1 = add2(v10, shx(v11, 4));
            r0 = add2(r0, shx(r0, 8));   r1 = add2(r1, shx(r1, 8));
            r0 = add2(r0, shx(r0, 16));  r1 = add2(r1, shx(r1, 16));
            if (mychunk == bi) { keep0 = r0; keep1 = r1; }
        }
        {
            keep0 = add2(keep0, preC);           // pre0 includes bias0
            float f0, f1;
            unpack2(keep0, f0, f1);
            *reinterpret_cast<u64*>(&h0s[p][sto]) = pack2(ftanh(f0), ftanh(f1));
        }
        if (t > 0) {                             // h1(-1) stays 0
            keep1 = add2(keep1, bz1);
            float f0, f1;
            unpack2(keep1, f0, f1);
            *reinterpret_cast<u64*>(&h1s[p][sto]) = pack2(ftanh(f0), ftanh(f1));
        }
        preC = preN;
        __syncthreads();                         // the ONE barrier per phase
    }

    // Epilogue phase (t=TT): L1 only -> h1(TT-1) into h1s[0]
    {
        u64 keep1;
#pragma unroll
        for (int bi = 0; bi < 4; bi++) {
            const u64* qa0 = reinterpret_cast<const u64*>(&h0s[1][ofA0 + bi*256]);
            const u64* qb0 = reinterpret_cast<const u64*>(&h0s[1][ofB0 + bi*256]);
            const u64 u0 = qa0[0], u1 = qa0[1], u2 = qb0[0], u3 = qb0[1];
            u64 a1[2][2];
#pragma unroll
            for (int q = 0; q < 2; q++)
#pragma unroll
                for (int h = 0; h < 2; h++) {
                    a1[q][h] = mul2(wb[q][h][0], u0);
                    fma2(a1[q][h], wb[q][h][1], u1);
                    fma2(a1[q][h], wb[q][h][2], u2);
                    fma2(a1[q][h], wb[q][h][3], u3);
                }
            const u64* qa1 = reinterpret_cast<const u64*>(&h1s[1][ofA0 + bi*256]);
            const u64* qb1 = reinterpret_cast<const u64*>(&h1s[1][ofB0 + bi*256]);
            const u64 z0 = qa1[0], z1 = qa1[1], z2 = qb1[0], z3 = qb1[1];
#pragma unroll
            for (int q = 0; q < 2; q++)
#pragma unroll
                for (int h = 0; h < 2; h++) {
                    fma2(a1[q][h], wc[q][h][0], z0);
                    fma2(a1[q][h], wc[q][h][1], z1);
                    fma2(a1[q][h], wc[q][h][2], z2);
                    fma2(a1[q][h], wc[q][h][3], z3);
                }
            u64 v10, v11;
            {
                float l0,m0,l1,m1;
                unpack2(a1[0][0],l0,m0); unpack2(a1[0][1],l1,m1);
                v10 = pack2(l0+m0, l1+m1);
                unpack2(a1[1][0],l0,m0); unpack2(a1[1][1],l1,m1);
                v11 = pack2(l0+m0, l1+m1);
            }
            u64 r1 = add2(v10, shx(v11, 4));
            r1 = add2(r1, shx(r1, 8));
            r1 = add2(r1, shx(r1, 16));
            if (mychunk == bi) keep1 = r1;
        }
        keep1 = add2(keep1, bz1);
        float f0, f1;
        unpack2(keep1, f0, f1);
        *reinterpret_cast<u64*>(&h1s[0][sto]) = pack2(ftanh(f0), ftanh(f1));
    }
    __syncthreads();

    // FC: out[b] = h1(T-1) . fcw + fcb   (h1(T-1) is in h1s[0])
    if (tid < 16) {
        const int gg = (tid & 1) | ((tid & 2) << 1);
        float sum = fcb[0];
#pragma unroll
        for (int q = 0; q < 16; q++) {
            const float4 hv = *reinterpret_cast<const float4*>(
                &h1s[0][tid * 64 + (((q + gg) & 15) << 2)]);
            const float4 wv = reinterpret_cast<const float4*>(fcw)[q];
            sum += hv.x * wv.x + hv.y * wv.y + hv.z * wv.z + hv.w * wv.w;
        }
        out[blockIdx.x * 16 + tid] = sum;
    }
}

extern "C" void kernel_launch(void* const* d_in, const int* in_sizes, int n_in,
                              void* d_out, int out_size)
{
    // Inputs: x, W_ih0, W_hh0, b_ih0, b_hh0, W_ih1, W_hh1, b_ih1, b_hh1, fc_w, fc_b
    (void)in_sizes; (void)n_in; (void)out_size;

    pre0_kernel<<<65536, 256>>>(
        (const float*)d_in[0], (const float*)d_in[1],
        (const float*)d_in[3], (const float*)d_in[4]);

    rnn_main<<<128, 512>>>(
        (const float*)d_in[2], (const float*)d_in[5], (const float*)d_in[6],
        (const float*)d_in[7], (const float*)d_in[8],
        (const float*)d_in[9], (const float*)d_in[10],
        (float*)d_out);
}